// round 12
// baseline (speedup 1.0000x reference)
#include <cuda_runtime.h>
#include <cuda_fp16.h>
#include <cstdint>

#define N 8192
#define H 512
#define SCALE 0.044194173824159216f   // 1/sqrt(512)

// ---------------- global scratch (no allocation allowed) -------------------
__device__ float g_khT[H * N];        // kh [h][node], original order
__device__ float g_kh [N * H];        // kh row-major, original order
__device__ float g_vh [N * H];        // vh row-major, original order
__device__ int   g_bucket[N];
__device__ int   g_perm[N];
__device__ int   g_bsorted[N];
__device__ int   g_chist[32 * 4];
__device__ int   g_bstart[5];
__device__ __half g_kh16h[N * H];     // kh sorted, row-major, fp16 split
__device__ __half g_kh16l[N * H];
__device__ __half g_vt16h[H * N];     // vh^T sorted: [h][pos], fp16 split
__device__ __half g_vt16l[H * N];

// ---------------- mma.sync m16n8k16 f16 -> f32 -----------------------------
__device__ __forceinline__ void mma16816h(float* c, const uint32_t* a,
                                          uint32_t b0, uint32_t b1) {
    asm volatile(
        "mma.sync.aligned.m16n8k16.row.col.f32.f16.f16.f32 "
        "{%0,%1,%2,%3}, {%4,%5,%6,%7}, {%8,%9}, {%0,%1,%2,%3};"
        : "+f"(c[0]), "+f"(c[1]), "+f"(c[2]), "+f"(c[3])
        : "r"(a[0]), "r"(a[1]), "r"(a[2]), "r"(a[3]), "r"(b0), "r"(b1));
}
__device__ __forceinline__ uint32_t packh2(float x, float y) {
    __half2 h = __floats2half2_rn(x, y);
    return *(uint32_t*)&h;
}
#define CP16(dst, src) \
    asm volatile("cp.async.cg.shared.global [%0], [%1], 16;" :: "r"(dst), "l"(src))
#define CP_COMMIT() asm volatile("cp.async.commit_group;")
#define CP_WAIT0()  asm volatile("cp.async.wait_group 0;")

// ---------------------------------------------------------------------------
// Producer: kh = X@kW (khT + kh row-major), vh = X@vW (row-major)
// ---------------------------------------------------------------------------
__global__ __launch_bounds__(128) void producer_kernel(const float* __restrict__ A,
                                                       const float* __restrict__ kW,
                                                       const float* __restrict__ vW) {
    const float* B = blockIdx.z ? vW : kW;
    __shared__ float At[16][64];
    __shared__ float Bt[16][128];
    int t = threadIdx.x;
    int tx = t & 15, ty = t >> 4;
    int r0 = blockIdx.x * 64, c0 = blockIdx.y * 128;

    float acc[8][8];
#pragma unroll
    for (int i = 0; i < 8; i++)
#pragma unroll
        for (int j = 0; j < 8; j++) acc[i][j] = 0.f;

    for (int kk = 0; kk < H; kk += 16) {
#pragma unroll
        for (int x = 0; x < 2; x++) {
            int fid = t + x * 128;
            int r = fid >> 2, c4 = fid & 3;
            float4 v = *(const float4*)&A[(r0 + r) * H + kk + c4 * 4];
            At[c4 * 4 + 0][r] = v.x; At[c4 * 4 + 1][r] = v.y;
            At[c4 * 4 + 2][r] = v.z; At[c4 * 4 + 3][r] = v.w;
        }
#pragma unroll
        for (int x = 0; x < 4; x++) {
            int fid = t + x * 128;
            int k = fid >> 5, cv = fid & 31;
            *(float4*)&Bt[k][cv * 4] = *(const float4*)&B[(kk + k) * 512 + c0 + cv * 4];
        }
        __syncthreads();
#pragma unroll
        for (int k = 0; k < 16; k++) {
            float a[8], b[8];
            *(float4*)(a)     = *(float4*)&At[k][ty * 8];
            *(float4*)(a + 4) = *(float4*)&At[k][ty * 8 + 4];
            *(float4*)(b)     = *(float4*)&Bt[k][tx * 8];
            *(float4*)(b + 4) = *(float4*)&Bt[k][tx * 8 + 4];
#pragma unroll
            for (int i = 0; i < 8; i++)
#pragma unroll
                for (int j = 0; j < 8; j++) acc[i][j] = fmaf(a[i], b[j], acc[i][j]);
        }
        __syncthreads();
    }

    if (blockIdx.z == 0) {
#pragma unroll
        for (int i = 0; i < 8; i++) {
#pragma unroll
            for (int j = 0; j < 8; j++)
                g_khT[(c0 + tx * 8 + j) * N + r0 + ty * 8 + i] = acc[i][j];
            int base = (r0 + ty * 8 + i) * H + c0 + tx * 8;
            *(float4*)&g_kh[base]     = make_float4(acc[i][0], acc[i][1], acc[i][2], acc[i][3]);
            *(float4*)&g_kh[base + 4] = make_float4(acc[i][4], acc[i][5], acc[i][6], acc[i][7]);
        }
    } else {
#pragma unroll
        for (int i = 0; i < 8; i++) {
            int base = (r0 + ty * 8 + i) * H + c0 + tx * 8;
            *(float4*)&g_vh[base]     = make_float4(acc[i][0], acc[i][1], acc[i][2], acc[i][3]);
            *(float4*)&g_vh[base + 4] = make_float4(acc[i][4], acc[i][5], acc[i][6], acc[i][7]);
        }
    }
}

// ---------------------------------------------------------------------------
__global__ void bucket_kernel(const float* __restrict__ rot) {
    int n = blockIdx.x * 256 + threadIdx.x;
    float v0 = 0.f, v1 = 0.f;
#pragma unroll 8
    for (int h = 0; h < H; h++) {
        float k = g_khT[h * N + n];
        v0 = fmaf(k, rot[h * 2 + 0], v0);
        v1 = fmaf(k, rot[h * 2 + 1], v1);
    }
    float best = v0; int b = 0;
    if (v1  > best) { best = v1;  b = 1; }
    if (-v0 > best) { best = -v0; b = 2; }
    if (-v1 > best) {             b = 3; }
    g_bucket[n] = b;
}

__global__ void hist_kernel() {
    __shared__ int h[4];
    int t = threadIdx.x;
    if (t < 4) h[t] = 0;
    __syncthreads();
    atomicAdd(&h[g_bucket[blockIdx.x * 256 + t]], 1);
    __syncthreads();
    if (t < 4) g_chist[blockIdx.x * 4 + t] = h[t];
}

__global__ void scatter_kernel() {
    __shared__ int lb[256];
    __shared__ int chs[128];
    int t = threadIdx.x, c = blockIdx.x;
    int node = c * 256 + t;
    int b = g_bucket[node];
    lb[t] = b;
    if (t < 128) chs[t] = g_chist[t];
    __syncthreads();

    int tot[4] = {0, 0, 0, 0};
    int pri = 0;
    for (int cc = 0; cc < 32; cc++) {
        if (cc < c) pri += chs[cc * 4 + b];
        tot[0] += chs[cc * 4 + 0]; tot[1] += chs[cc * 4 + 1];
        tot[2] += chs[cc * 4 + 2]; tot[3] += chs[cc * 4 + 3];
    }
    int bs = 0;
    for (int bb = 0; bb < 4; bb++) if (bb < b) bs += tot[bb];
    int r = 0;
    for (int j = 0; j < t; j++) r += (lb[j] == b);
    int pos = bs + pri + r;
    g_perm[pos] = node;
    g_bsorted[pos] = b;

    if (c == 0 && t < 4) {
        int s = 0;
        for (int bb = 0; bb < t; bb++) s += tot[bb];
        g_bstart[t] = s;
        if (t == 0) g_bstart[4] = N;
    }
}

// fp16 split converts (sorted order)
__global__ void conv_kh_kernel() {
    int idx = blockIdx.x * 256 + threadIdx.x;          // over N*H, h fastest
    int pos = idx >> 9, h = idx & 511;
    float v = g_kh[g_perm[pos] * H + h];
    __half hi = __float2half_rn(v);
    g_kh16h[idx] = hi;
    g_kh16l[idx] = __float2half_rn(v - __half2float(hi));
}
__global__ void conv_vT_kernel() {
    int idx = blockIdx.x * 256 + threadIdx.x;          // over H*N, pos fastest
    int h = idx >> 13, pos = idx & 8191;
    float v = g_vh[g_perm[pos] * H + h];
    __half hi = __float2half_rn(v);
    g_vt16h[idx] = hi;
    g_vt16l[idx] = __float2half_rn(v - __half2float(hi));
}

// ---------------------------------------------------------------------------
// Fused block-diagonal attention: fp16 mma, flash-style online row max.
// GEMM1: 16 chunks BK=32, Q/K fp16 hi+lo, 3 products, cp.async depth-1.
// Softmax: p' = exp(e - m_row), m_row = running max; O,lsum rescaled by
// exp(m_old - m_new) when max grows.  P stored fp16 (values in (0,1]).
// GEMM2: 16 chunks of 32 H-cols, V fp16 hi+lo, 2 products.
// ---------------------------------------------------------------------------
__global__ __launch_bounds__(256) void attn_kernel(const int* __restrict__ adj,
                                                   float* __restrict__ out) {
    extern __shared__ char sm[];
    float*   Os   = (float*)sm;                    // [64][520]  133120 B
    __half*  Ph   = (__half*)(sm + 133120);        // [64][136]  17408 B
    const int OVL = 150528;                        // staging 61440 B
    // GEMM1 stage s at OVL+s*30720: Qh 0, Ql 5120, Kh 10240, Kl 20480 (pitch 80B)
    // GEMM2 stage s at OVL+s*17408: Vh 0, Vl 8704 (pitch 272B)
    int*      bc   = (int*)(sm + 211968);          // [128]
    int*      pc   = (int*)(sm + 212480);          // [128]
    int*      pr   = (int*)(sm + 212992);          // [64]
    int*      brr  = (int*)(sm + 213248);          // [64]
    uint32_t* mw   = (uint32_t*)(sm + 213504);     // [64][4]
    float*    mrow = (float*)(sm + 214528);        // [64]
    float*    cfac = (float*)(sm + 214784);        // [64]
    float*    rmx  = (float*)(sm + 215040);        // [2][64]
    float*    lrh  = (float*)(sm + 215552);        // [2][64]

    uint32_t sb = (uint32_t)__cvta_generic_to_shared(sm);
    int t = threadIdx.x, w = t >> 5, lane = t & 31;
    int g = lane >> 2, tig = lane & 3;
    int rb16 = (w & 3) * 16;
    int ch   = w >> 2;                 // col half (0/1)
    int row0 = blockIdx.x * 64;

    for (int i = t; i < 64 * 520; i += 256) Os[i] = 0.f;
    if (t < 64) {
        pr[t] = g_perm[row0 + t];
        brr[t] = g_bsorted[row0 + t];
        mrow[t] = -1e30f;
    }
    __syncthreads();

    int cstart = g_bstart[brr[0]];
    int cend   = g_bstart[brr[63] + 1];
    int cbase0 = cstart & ~127;
    float lsum0 = 0.f, lsum1 = 0.f;
    int r0w = rb16 + g, r1w = rb16 + g + 8;
    int qr = t >> 2, qs = t & 3;       // Q/K cp mapping: row, 16B-seg

    for (int col0 = cbase0; col0 < cend; col0 += 128) {
        __syncthreads();
        if (t < 128) { bc[t] = g_bsorted[col0 + t]; pc[t] = g_perm[col0 + t]; }
        __syncthreads();

        // ---- issue GEMM1 chunk 0 (overlaps adj gathers) ----
        {
            uint32_t st = sb + OVL;
            CP16(st + qr * 80 + qs * 16,        &g_kh16h[(size_t)(row0 + qr) * H + qs * 8]);
            CP16(st + 5120 + qr * 80 + qs * 16, &g_kh16l[(size_t)(row0 + qr) * H + qs * 8]);
#pragma unroll
            for (int x = 0; x < 2; x++) {
                int fid = t + x * 256;
                int r = fid >> 2, s2 = fid & 3;
                CP16(st + 10240 + r * 80 + s2 * 16, &g_kh16h[(size_t)(col0 + r) * H + s2 * 8]);
                CP16(st + 20480 + r * 80 + s2 * 16, &g_kh16l[(size_t)(col0 + r) * H + s2 * 8]);
            }
            CP_COMMIT();
        }

        // ---- mask bitwords ----
        {
            int r = t >> 2, wb = t & 3;
            const int* arow = adj + (size_t)pr[r] * N;
            int rbv = brr[r];
            uint32_t m = 0;
#pragma unroll
            for (int c = 0; c < 32; c++) {
                int ci = wb * 32 + c;
                if ((bc[ci] == rbv) && (arow[pc[ci]] > 0)) m |= (1u << c);
            }
            mw[t] = m;
        }

        // ---- GEMM1: 16 chunks of BK=32, depth-1 pipeline, 3 products ----
        float sf[8][4];
#pragma unroll
        for (int nb = 0; nb < 8; nb++)
#pragma unroll
            for (int i = 0; i < 4; i++) sf[nb][i] = 0.f;

#pragma unroll 1
        for (int c = 0; c < 16; c++) {
            CP_WAIT0();
            __syncthreads();
            if (c + 1 < 16) {
                int kk = (c + 1) * 32;
                uint32_t st = sb + OVL + ((c + 1) & 1) * 30720;
                CP16(st + qr * 80 + qs * 16,        &g_kh16h[(size_t)(row0 + qr) * H + kk + qs * 8]);
                CP16(st + 5120 + qr * 80 + qs * 16, &g_kh16l[(size_t)(row0 + qr) * H + kk + qs * 8]);
#pragma unroll
                for (int x = 0; x < 2; x++) {
                    int fid = t + x * 256;
                    int r = fid >> 2, s2 = fid & 3;
                    CP16(st + 10240 + r * 80 + s2 * 16, &g_kh16h[(size_t)(col0 + r) * H + kk + s2 * 8]);
                    CP16(st + 20480 + r * 80 + s2 * 16, &g_kh16l[(size_t)(col0 + r) * H + kk + s2 * 8]);
                }
                CP_COMMIT();
            }
            const __half* Qh = (const __half*)(sm + OVL + (c & 1) * 30720);
            const __half* Ql = Qh + 2560;
            const __half* Kh = Qh + 5120;
            const __half* Kl = Qh + 10240;
#pragma unroll
            for (int ks = 0; ks < 2; ks++) {
                int kb = ks * 16 + 2 * tig;
                uint32_t ah[4], al[4];
                const __half* q = &Qh[r0w * 40 + kb];
                ah[0] = *(const uint32_t*)q;
                ah[1] = *(const uint32_t*)(q + 320);
                ah[2] = *(const uint32_t*)(q + 8);
                ah[3] = *(const uint32_t*)(q + 328);
                const __half* ql = &Ql[r0w * 40 + kb];
                al[0] = *(const uint32_t*)ql;
                al[1] = *(const uint32_t*)(ql + 320);
                al[2] = *(const uint32_t*)(ql + 8);
                al[3] = *(const uint32_t*)(ql + 328);
#pragma unroll
                for (int nb = 0; nb < 8; nb++) {
                    const __half* kp = &Kh[(ch * 64 + nb * 8 + g) * 40 + kb];
                    uint32_t bh0 = *(const uint32_t*)kp;
                    uint32_t bh1 = *(const uint32_t*)(kp + 8);
                    const __half* kl = &Kl[(ch * 64 + nb * 8 + g) * 40 + kb];
                    uint32_t bl0 = *(const uint32_t*)kl;
                    uint32_t bl1 = *(const uint32_t*)(kl + 8);
                    mma16816h(sf[nb], ah, bh0, bh1);
                    mma16816h(sf[nb], ah, bl0, bl1);
                    mma16816h(sf[nb], al, bh0, bh1);
                }
            }
        }

        // ---- mask -> exponent units; per-row tile max ----
        float tmax0 = -1e30f, tmax1 = -1e30f;
#pragma unroll
        for (int nb = 0; nb < 8; nb++) {
            int col = ch * 64 + nb * 8 + 2 * tig;
            uint32_t m0 = mw[r0w * 4 + (col >> 5)];
            uint32_t m1 = mw[r1w * 4 + (col >> 5)];
            int bi = col & 31;
            sf[nb][0] = ((m0 >> bi) & 1)       ? sf[nb][0] * SCALE : -1e30f;
            sf[nb][1] = ((m0 >> (bi + 1)) & 1) ? sf[nb][1] * SCALE : -1e30f;
            sf[nb][2] = ((m1 >> bi) & 1)       ? sf[nb][2] * SCALE : -1e30f;
            sf[nb][3] = ((m1 >> (bi + 1)) & 1) ? sf[nb][3] * SCALE : -1e30f;
            tmax0 = fmaxf(tmax0, fmaxf(sf[nb][0], sf[nb][1]));
            tmax1 = fmaxf(tmax1, fmaxf(sf[nb][2], sf[nb][3]));
        }
        tmax0 = fmaxf(tmax0, __shfl_xor_sync(0xFFFFFFFFu, tmax0, 1));
        tmax0 = fmaxf(tmax0, __shfl_xor_sync(0xFFFFFFFFu, tmax0, 2));
        tmax1 = fmaxf(tmax1, __shfl_xor_sync(0xFFFFFFFFu, tmax1, 1));
        tmax1 = fmaxf(tmax1, __shfl_xor_sync(0xFFFFFFFFu, tmax1, 2));
        if (tig == 0) {
            rmx[ch * 64 + r0w] = tmax0;
            rmx[ch * 64 + r1w] = tmax1;
        }
        __syncthreads();
        if (t < 64) {
            float mo = mrow[t];
            float mn = fmaxf(mo, fmaxf(rmx[t], rmx[64 + t]));
            cfac[t] = __expf(mo - mn);     // -1e30 - mn -> 0; mo==mn -> 1
            mrow[t] = mn;
        }
        int allone = __syncthreads_and((t < 64) ? (cfac[t] == 1.0f) : 1);
        if (!allone) {
#pragma unroll 1
            for (int x = 0; x < 32; x++) {
                int fid = t + x * 256;
                int r = fid >> 7, c4 = fid & 127;
                float cr = cfac[r];
                float4 v = *(float4*)&Os[r * 520 + c4 * 4];
                v.x *= cr; v.y *= cr; v.z *= cr; v.w *= cr;
                *(float4*)&Os[r * 520 + c4 * 4] = v;
            }
        }

        // ---- p' = exp(e - m_row) -> Ph (fp16) + rescaled lsum ----
        float mn0 = mrow[r0w], mn1 = mrow[r1w];
        lsum0 *= cfac[r0w];
        lsum1 *= cfac[r1w];
#pragma unroll
        for (int nb = 0; nb < 8; nb++) {
            int col = ch * 64 + nb * 8 + 2 * tig;
            float p00 = __expf(sf[nb][0] - mn0);
            float p01 = __expf(sf[nb][1] - mn0);
            float p10 = __expf(sf[nb][2] - mn1);
            float p11 = __expf(sf[nb][3] - mn1);
            lsum0 += p00 + p01;
            lsum1 += p10 + p11;
            *(uint32_t*)&Ph[r0w * 136 + col] = packh2(p00, p01);
            *(uint32_t*)&Ph[r1w * 136 + col] = packh2(p10, p11);
        }
        __syncthreads();   // P + Os-rescale done; GEMM1 staging free

        // ---- issue V(hc=0); hoist P frags to registers ----
#pragma unroll
        for (int x = 0; x < 2; x++) {
            int fid = t + x * 256;
            int r = fid >> 4, s = fid & 15;
            uint32_t st = sb + OVL;
            CP16(st + r * 272 + s * 16,        &g_vt16h[(size_t)r * N + col0 + s * 8]);
            CP16(st + 8704 + r * 272 + s * 16, &g_vt16l[(size_t)r * N + col0 + s * 8]);
        }
        CP_COMMIT();

        uint32_t pa[8][4];
#pragma unroll
        for (int ks = 0; ks < 8; ks++) {
            int kb = ks * 16 + 2 * tig;
            const __half* p = &Ph[r0w * 136 + kb];
            pa[ks][0] = *(const uint32_t*)p;
            pa[ks][1] = *(const uint32_t*)(p + 8 * 136);
            pa[ks][2] = *(const uint32_t*)(p + 8);
            pa[ks][3] = *(const uint32_t*)(p + 8 * 136 + 8);
        }

        // ---- GEMM2: 16 chunks of 32 H-cols, 2 products ----
        int ch2 = ch * 16;
#pragma unroll 1
        for (int hc = 0; hc < 16; hc++) {
            CP_WAIT0();
            __syncthreads();
            if (hc + 1 < 16) {
                uint32_t st = sb + OVL + ((hc + 1) & 1) * 17408;
#pragma unroll
                for (int x = 0; x < 2; x++) {
                    int fid = t + x * 256;
                    int r = fid >> 4, s = fid & 15;
                    CP16(st + r * 272 + s * 16,
                         &g_vt16h[(size_t)((hc + 1) * 32 + r) * N + col0 + s * 8]);
                    CP16(st + 8704 + r * 272 + s * 16,
                         &g_vt16l[(size_t)((hc + 1) * 32 + r) * N + col0 + s * 8]);
                }
                CP_COMMIT();
            }
            const __half* Vh = (const __half*)(sm + OVL + (hc & 1) * 17408);
            const __half* Vl = Vh + 4352;

            float cf[2][4];
            int ob = r0w * 520 + hc * 32 + ch2;
#pragma unroll
            for (int nb = 0; nb < 2; nb++) {
                float2 v0 = *(float2*)&Os[ob + nb * 8 + 2 * tig];
                float2 v1 = *(float2*)&Os[ob + 8 * 520 + nb * 8 + 2 * tig];
                cf[nb][0] = v0.x; cf[nb][1] = v0.y;
                cf[nb][2] = v1.x; cf[nb][3] = v1.y;
            }
#pragma unroll
            for (int ks = 0; ks < 8; ks++) {
                int kb = ks * 16 + 2 * tig;
#pragma unroll
                for (int nb = 0; nb < 2; nb++) {
                    const __half* vp = &Vh[(ch2 + nb * 8 + g) * 136 + kb];
                    uint32_t bh0 = *(const uint32_t*)vp;
                    uint32_t bh1 = *(const uint32_t*)(vp + 8);
                    const __half* vl = &Vl[(ch2 + nb * 8 + g) * 136 + kb];
                    uint32_t bl0 = *(const uint32_t*)vl;
                    uint32_t bl1 = *(const uint32_t*)(vl + 8);
                    mma16816h(cf[nb], pa[ks], bh0, bh1);
                    mma16816h(cf[nb], pa[ks], bl0, bl1);
                }
            }
#pragma unroll
            for (int nb = 0; nb < 2; nb++) {
                *(float2*)&Os[ob + nb * 8 + 2 * tig] = make_float2(cf[nb][0], cf[nb][1]);
                *(float2*)&Os[ob + 8 * 520 + nb * 8 + 2 * tig] = make_float2(cf[nb][2], cf[nb][3]);
            }
        }
    }

    // ---- lsum reduce (over tig) and publish ----
    lsum0 += __shfl_xor_sync(0xFFFFFFFFu, lsum0, 1);
    lsum0 += __shfl_xor_sync(0xFFFFFFFFu, lsum0, 2);
    lsum1 += __shfl_xor_sync(0xFFFFFFFFu, lsum1, 1);
    lsum1 += __shfl_xor_sync(0xFFFFFFFFu, lsum1, 2);
    if (tig == 0) {
        lrh[ch * 64 + r0w] = lsum0;
        lrh[ch * 64 + r1w] = lsum1;
    }
    __syncthreads();

    // ---- epilogue: normalize + ELU + scatter rows to original order ----
#pragma unroll 1
    for (int x = 0; x < 32; x++) {
        int fid = t + x * 256;
        int r = fid >> 7, c4 = fid & 127;
        float inv = 1.f / (lrh[r] + lrh[64 + r]);
        float4 v = *(float4*)&Os[r * 520 + c4 * 4];
        v.x *= inv; v.y *= inv; v.z *= inv; v.w *= inv;
        v.x = v.x > 0.f ? v.x : expm1f(v.x);
        v.y = v.y > 0.f ? v.y : expm1f(v.y);
        v.z = v.z > 0.f ? v.z : expm1f(v.z);
        v.w = v.w > 0.f ? v.w : expm1f(v.w);
        *(float4*)&out[(size_t)pr[r] * H + c4 * 4] = v;
    }
}

// ---------------------------------------------------------------------------
extern "C" void kernel_launch(void* const* d_in, const int* in_sizes, int n_in,
                              void* d_out, int out_size) {
    const float* input = (const float*)d_in[0];
    const int*   adj   = (const int*)d_in[1];
    const float* rot   = (const float*)d_in[2];
    const float* kW    = (const float*)d_in[3];
    const float* vW    = (const float*)d_in[4];
    float* out = (float*)d_out;

    const int smem_bytes = 216064;
    cudaFuncSetAttribute(attn_kernel, cudaFuncAttributeMaxDynamicSharedMemorySize,
                         smem_bytes);

    producer_kernel<<<dim3(N / 64, H / 128, 2), 128>>>(input, kW, vW);
    bucket_kernel<<<N / 256, 256>>>(rot);
    hist_kernel<<<32, 256>>>();
    scatter_kernel<<<32, 256>>>();
    conv_kh_kernel<<<(N * H) / 256, 256>>>();
    conv_vT_kernel<<<(H * N) / 256, 256>>>();
    attn_kernel<<<N / 64, 256, smem_bytes>>>(adj, out);
}

// round 13
// speedup vs baseline: 1.2662x; 1.2662x over previous
#include <cuda_runtime.h>
#include <cuda_bf16.h>
#include <cstdint>

#define N 8192
#define H 512
#define SCALE 0.044194173824159216f   // 1/sqrt(512)
#define SHIFT 50.0f

// ---------------- global scratch (no allocation allowed) -------------------
__device__ float g_khT[H * N];        // kh [h][node], original order
__device__ float g_kh [N * H];        // kh row-major, original order
__device__ float g_vh [N * H];        // vh row-major, original order
__device__ int   g_bucket[N];
__device__ int   g_perm[N];
__device__ int   g_bsorted[N];
__device__ int   g_chist[32 * 4];
__device__ int   g_bstart[5];
__device__ __nv_bfloat16 g_khb_hi[N * H];   // kh sorted, row-major [pos][h]
__device__ __nv_bfloat16 g_khb_lo[N * H];
__device__ __nv_bfloat16 g_vT_hi[H * N];    // vh^T sorted: [h][pos]
__device__ __nv_bfloat16 g_vT_lo[H * N];

// ---------------- mma.sync m16n8k16 bf16 -> f32 ----------------------------
__device__ __forceinline__ void mma16816(float* c, const uint32_t* a,
                                         uint32_t b0, uint32_t b1) {
    asm volatile(
        "mma.sync.aligned.m16n8k16.row.col.f32.bf16.bf16.f32 "
        "{%0,%1,%2,%3}, {%4,%5,%6,%7}, {%8,%9}, {%0,%1,%2,%3};"
        : "+f"(c[0]), "+f"(c[1]), "+f"(c[2]), "+f"(c[3])
        : "r"(a[0]), "r"(a[1]), "r"(a[2]), "r"(a[3]), "r"(b0), "r"(b1));
}
__device__ __forceinline__ void ldsm4(uint32_t* r, uint32_t addr) {
    asm volatile("ldmatrix.sync.aligned.m8n8.x4.shared.b16 {%0,%1,%2,%3}, [%4];"
        : "=r"(r[0]), "=r"(r[1]), "=r"(r[2]), "=r"(r[3]) : "r"(addr));
}
__device__ __forceinline__ uint32_t packbf(float x, float y) {
    __nv_bfloat16 hx = __float2bfloat16(x), hy = __float2bfloat16(y);
    return (uint32_t)__bfloat16_as_ushort(hx) |
           ((uint32_t)__bfloat16_as_ushort(hy) << 16);
}
#define CP16(dst, src) \
    asm volatile("cp.async.cg.shared.global [%0], [%1], 16;" :: "r"(dst), "l"(src))
#define CP_COMMIT() asm volatile("cp.async.commit_group;")
#define CP_WAIT0()  asm volatile("cp.async.wait_group 0;")

// ---------------------------------------------------------------------------
// Producer: kh = X@kW (khT + kh row-major), vh = X@vW (row-major)
// ---------------------------------------------------------------------------
__global__ __launch_bounds__(128) void producer_kernel(const float* __restrict__ A,
                                                       const float* __restrict__ kW,
                                                       const float* __restrict__ vW) {
    const float* B = blockIdx.z ? vW : kW;
    __shared__ float At[16][64];
    __shared__ float Bt[16][128];
    int t = threadIdx.x;
    int tx = t & 15, ty = t >> 4;
    int r0 = blockIdx.x * 64, c0 = blockIdx.y * 128;

    float acc[8][8];
#pragma unroll
    for (int i = 0; i < 8; i++)
#pragma unroll
        for (int j = 0; j < 8; j++) acc[i][j] = 0.f;

    for (int kk = 0; kk < H; kk += 16) {
#pragma unroll
        for (int x = 0; x < 2; x++) {
            int fid = t + x * 128;
            int r = fid >> 2, c4 = fid & 3;
            float4 v = *(const float4*)&A[(r0 + r) * H + kk + c4 * 4];
            At[c4 * 4 + 0][r] = v.x; At[c4 * 4 + 1][r] = v.y;
            At[c4 * 4 + 2][r] = v.z; At[c4 * 4 + 3][r] = v.w;
        }
#pragma unroll
        for (int x = 0; x < 4; x++) {
            int fid = t + x * 128;
            int k = fid >> 5, cv = fid & 31;
            *(float4*)&Bt[k][cv * 4] = *(const float4*)&B[(kk + k) * 512 + c0 + cv * 4];
        }
        __syncthreads();
#pragma unroll
        for (int k = 0; k < 16; k++) {
            float a[8], b[8];
            *(float4*)(a)     = *(float4*)&At[k][ty * 8];
            *(float4*)(a + 4) = *(float4*)&At[k][ty * 8 + 4];
            *(float4*)(b)     = *(float4*)&Bt[k][tx * 8];
            *(float4*)(b + 4) = *(float4*)&Bt[k][tx * 8 + 4];
#pragma unroll
            for (int i = 0; i < 8; i++)
#pragma unroll
                for (int j = 0; j < 8; j++) acc[i][j] = fmaf(a[i], b[j], acc[i][j]);
        }
        __syncthreads();
    }

    if (blockIdx.z == 0) {
#pragma unroll
        for (int i = 0; i < 8; i++) {
#pragma unroll
            for (int j = 0; j < 8; j++)
                g_khT[(c0 + tx * 8 + j) * N + r0 + ty * 8 + i] = acc[i][j];
            int base = (r0 + ty * 8 + i) * H + c0 + tx * 8;
            *(float4*)&g_kh[base]     = make_float4(acc[i][0], acc[i][1], acc[i][2], acc[i][3]);
            *(float4*)&g_kh[base + 4] = make_float4(acc[i][4], acc[i][5], acc[i][6], acc[i][7]);
        }
    } else {
#pragma unroll
        for (int i = 0; i < 8; i++) {
            int base = (r0 + ty * 8 + i) * H + c0 + tx * 8;
            *(float4*)&g_vh[base]     = make_float4(acc[i][0], acc[i][1], acc[i][2], acc[i][3]);
            *(float4*)&g_vh[base + 4] = make_float4(acc[i][4], acc[i][5], acc[i][6], acc[i][7]);
        }
    }
}

// ---------------------------------------------------------------------------
__global__ void bucket_kernel(const float* __restrict__ rot) {
    int n = blockIdx.x * 256 + threadIdx.x;
    float v0 = 0.f, v1 = 0.f;
#pragma unroll 8
    for (int h = 0; h < H; h++) {
        float k = g_khT[h * N + n];
        v0 = fmaf(k, rot[h * 2 + 0], v0);
        v1 = fmaf(k, rot[h * 2 + 1], v1);
    }
    float best = v0; int b = 0;
    if (v1  > best) { best = v1;  b = 1; }
    if (-v0 > best) { best = -v0; b = 2; }
    if (-v1 > best) {             b = 3; }
    g_bucket[n] = b;
}

__global__ void hist_kernel() {
    __shared__ int h[4];
    int t = threadIdx.x;
    if (t < 4) h[t] = 0;
    __syncthreads();
    atomicAdd(&h[g_bucket[blockIdx.x * 256 + t]], 1);
    __syncthreads();
    if (t < 4) g_chist[blockIdx.x * 4 + t] = h[t];
}

__global__ void scatter_kernel() {
    __shared__ int lb[256];
    __shared__ int chs[128];
    int t = threadIdx.x, c = blockIdx.x;
    int node = c * 256 + t;
    int b = g_bucket[node];
    lb[t] = b;
    if (t < 128) chs[t] = g_chist[t];
    __syncthreads();

    int tot[4] = {0, 0, 0, 0};
    int pri = 0;
    for (int cc = 0; cc < 32; cc++) {
        if (cc < c) pri += chs[cc * 4 + b];
        tot[0] += chs[cc * 4 + 0]; tot[1] += chs[cc * 4 + 1];
        tot[2] += chs[cc * 4 + 2]; tot[3] += chs[cc * 4 + 3];
    }
    int bs = 0;
    for (int bb = 0; bb < 4; bb++) if (bb < b) bs += tot[bb];
    int r = 0;
    for (int j = 0; j < t; j++) r += (lb[j] == b);
    int pos = bs + pri + r;
    g_perm[pos] = node;
    g_bsorted[pos] = b;

    if (c == 0 && t < 4) {
        int s = 0;
        for (int bb = 0; bb < t; bb++) s += tot[bb];
        g_bstart[t] = s;
        if (t == 0) g_bstart[4] = N;
    }
}

// bf16 split converts (sorted order)
__global__ void conv_kh_kernel() {
    int idx = blockIdx.x * 256 + threadIdx.x;          // over N*H, h fastest
    int pos = idx >> 9, h = idx & 511;
    float v = g_kh[g_perm[pos] * H + h];
    __nv_bfloat16 hi = __float2bfloat16(v);
    g_khb_hi[idx] = hi;
    g_khb_lo[idx] = __float2bfloat16(v - __bfloat162float(hi));
}
__global__ void conv_vT_kernel() {
    int idx = blockIdx.x * 256 + threadIdx.x;          // over H*N, pos fastest
    int h = idx >> 13, pos = idx & 8191;
    float v = g_vh[g_perm[pos] * H + h];
    __nv_bfloat16 hi = __float2bfloat16(v);
    g_vT_hi[idx] = hi;
    g_vT_lo[idx] = __float2bfloat16(v - __bfloat162float(hi));
}

// ---------------------------------------------------------------------------
// Fused block-diagonal attention, R11 numerics + ldmatrix fragment loading.
// GEMM1: 32 chunks BK=16, Q/K bf16 hi+lo, 3 products, cp.async depth-1,
//        frags via ldmatrix.x4.  P stored hi+lo.
// GEMM2: 16 chunks of 32 H-cols, V hi+lo, 3 products, P frags hoisted via
//        ldmatrix, V frags via ldmatrix.
// ---------------------------------------------------------------------------
__global__ __launch_bounds__(256) void attn_kernel(const int* __restrict__ adj,
                                                   float* __restrict__ out) {
    extern __shared__ char sm[];
    float*          Os  = (float*)sm;                      // [64][520] 133120B
    __nv_bfloat16*  Phi = (__nv_bfloat16*)(sm + 133120);   // [64][136] 17408B
    __nv_bfloat16*  Plo = (__nv_bfloat16*)(sm + 150528);   // [64][136] 17408B
    const int OVL = 167936;                                // 36864B staging
    // GEMM1 stage s (18432B): Qhi s*18432, Qlo +3072, Khi +6144, Klo +12288
    //   (pitch 24 halves = 48B)
    // GEMM2 stage s (17408B): Vhi s*17408, Vlo +8704 (pitch 136 halves = 272B)
    int*      bc  = (int*)(sm + 204800);                   // [128]
    int*      pc  = (int*)(sm + 205312);                   // [128]
    int*      pr  = (int*)(sm + 205824);                   // [64]
    int*      brr = (int*)(sm + 206080);                   // [64]
    uint32_t* mw  = (uint32_t*)(sm + 206336);              // [64][4]
    float*    lrh = (float*)(sm + 207360);                 // [2][64]

    uint32_t sb = (uint32_t)__cvta_generic_to_shared(sm);
    int t = threadIdx.x, w = t >> 5, lane = t & 31;
    int g = lane >> 2, tig = lane & 3;
    int rb16 = (w & 3) * 16;          // warp row block
    int ch   = w >> 2;                // GEMM1 col half (0/1)
    int row0 = blockIdx.x * 64;

    for (int i = t; i < 64 * 520; i += 256) Os[i] = 0.f;
    if (t < 64) { pr[t] = g_perm[row0 + t]; brr[t] = g_bsorted[row0 + t]; }
    __syncthreads();

    int cstart = g_bstart[brr[0]];
    int cend   = g_bstart[brr[63] + 1];
    int cbase0 = cstart & ~127;
    float lsum0 = 0.f, lsum1 = 0.f;
    int r0w = rb16 + g, r1w = rb16 + g + 8;

    // ---- ldmatrix per-lane byte offsets ----
    // A-frag (16 rows x 16 k), pitch 24 halves: row rb16+(l&15), koff (l>>4)*8
    uint32_t qld = (uint32_t)(((rb16 + (lane & 15)) * 24 + ((lane >> 4) * 8)) * 2);
    // B-frag pair (16 n-rows x 16 k), pitch 24: row n0+((l>>4)<<3)+(l&7),
    // koff ((l>>3)&1)*8;  n0 = ch*64 (+ nbp*16 added per call)
    uint32_t kld = (uint32_t)(((ch * 64 + ((lane >> 4) << 3) + (lane & 7)) * 24
                               + (((lane >> 3) & 1) * 8)) * 2);
    // P A-frag, pitch 136 halves
    uint32_t pld = (uint32_t)(((rb16 + (lane & 15)) * 136 + ((lane >> 4) * 8)) * 2);
    // V B-frag pair, pitch 136; n0 = ch2 = ch*16
    uint32_t vld = (uint32_t)(((ch * 16 + ((lane >> 4) << 3) + (lane & 7)) * 136
                               + (((lane >> 3) & 1) * 8)) * 2);

    // cp.async per-thread mapping (GEMM1): Q: r=t>>2 (64), sub=t&3
    int qr = t >> 2, qs = t & 3;
    int qhl = qs >> 1, qseg = qs & 1;

    for (int col0 = cbase0; col0 < cend; col0 += 128) {
        __syncthreads();
        if (t < 128) { bc[t] = g_bsorted[col0 + t]; pc[t] = g_perm[col0 + t]; }
        __syncthreads();

        // ---- issue GEMM1 chunk 0 loads (overlap with adj gathers below) ----
        {
            uint32_t st = sb + OVL;
            const __nv_bfloat16* qsrc = qhl ? g_khb_lo : g_khb_hi;
            CP16(st + qhl * 3072 + qr * 48 + qseg * 16,
                 &qsrc[(size_t)(row0 + qr) * H + qseg * 8]);
#pragma unroll
            for (int x = 0; x < 2; x++) {
                int fid = t + x * 256;
                int r = fid >> 2, s2 = fid & 3;
                const __nv_bfloat16* ksrc = (s2 >> 1) ? g_khb_lo : g_khb_hi;
                CP16(st + 6144 + (s2 >> 1) * 6144 + r * 48 + (s2 & 1) * 16,
                     &ksrc[(size_t)(col0 + r) * H + (s2 & 1) * 8]);
            }
            CP_COMMIT();
        }

        // ---- mask bitwords: row (t>>2), word (t&3); 32 adj gathers each ----
        {
            int r = t >> 2, wb = t & 3;
            const int* arow = adj + (size_t)pr[r] * N;
            int rbv = brr[r];
            uint32_t m = 0;
#pragma unroll
            for (int c = 0; c < 32; c++) {
                int ci = wb * 32 + c;
                if ((bc[ci] == rbv) && (arow[pc[ci]] > 0)) m |= (1u << c);
            }
            mw[t] = m;
        }

        // ---- GEMM1: S[64x128] = Q K^T, 32 chunks of 16, depth-1 pipeline ----
        float sf[8][4];
#pragma unroll
        for (int nb = 0; nb < 8; nb++)
#pragma unroll
            for (int i = 0; i < 4; i++) sf[nb][i] = 0.f;

#pragma unroll 1
        for (int c = 0; c < 32; c++) {
            CP_WAIT0();
            __syncthreads();
            if (c + 1 < 32) {
                int kk = (c + 1) * 16;
                uint32_t st = sb + OVL + ((c + 1) & 1) * 18432;
                const __nv_bfloat16* qsrc = qhl ? g_khb_lo : g_khb_hi;
                CP16(st + qhl * 3072 + qr * 48 + qseg * 16,
                     &qsrc[(size_t)(row0 + qr) * H + kk + qseg * 8]);
#pragma unroll
                for (int x = 0; x < 2; x++) {
                    int fid = t + x * 256;
                    int r = fid >> 2, s2 = fid & 3;
                    const __nv_bfloat16* ksrc = (s2 >> 1) ? g_khb_lo : g_khb_hi;
                    CP16(st + 6144 + (s2 >> 1) * 6144 + r * 48 + (s2 & 1) * 16,
                         &ksrc[(size_t)(col0 + r) * H + kk + (s2 & 1) * 8]);
                }
                CP_COMMIT();
            }
            uint32_t stQ = sb + OVL + (c & 1) * 18432;
            uint32_t ah[4], al[4];
            ldsm4(ah, stQ + qld);
            ldsm4(al, stQ + 3072 + qld);
#pragma unroll
            for (int nbp = 0; nbp < 4; nbp++) {
                uint32_t kh4[4], kl4[4];
                ldsm4(kh4, stQ + 6144 + kld + nbp * 768u);
                ldsm4(kl4, stQ + 12288 + kld + nbp * 768u);
                mma16816(sf[nbp * 2],     ah, kh4[0], kh4[1]);
                mma16816(sf[nbp * 2],     ah, kl4[0], kl4[1]);
                mma16816(sf[nbp * 2],     al, kh4[0], kh4[1]);
                mma16816(sf[nbp * 2 + 1], ah, kh4[2], kh4[3]);
                mma16816(sf[nbp * 2 + 1], ah, kl4[2], kl4[3]);
                mma16816(sf[nbp * 2 + 1], al, kh4[2], kh4[3]);
            }
        }

        // ---- mask + exp in-register -> Phi/Plo + lsum ----
#pragma unroll
        for (int nb = 0; nb < 8; nb++) {
            int col = ch * 64 + nb * 8 + 2 * tig;
            uint32_t m0 = mw[r0w * 4 + (col >> 5)];
            uint32_t m1 = mw[r1w * 4 + (col >> 5)];
            int bi = col & 31;
            float p00 = ((m0 >> bi) & 1)       ? __expf(fmaf(sf[nb][0], SCALE, -SHIFT)) : 0.f;
            float p01 = ((m0 >> (bi + 1)) & 1) ? __expf(fmaf(sf[nb][1], SCALE, -SHIFT)) : 0.f;
            float p10 = ((m1 >> bi) & 1)       ? __expf(fmaf(sf[nb][2], SCALE, -SHIFT)) : 0.f;
            float p11 = ((m1 >> (bi + 1)) & 1) ? __expf(fmaf(sf[nb][3], SCALE, -SHIFT)) : 0.f;
            lsum0 += p00 + p01;
            lsum1 += p10 + p11;
            *(uint32_t*)&Phi[r0w * 136 + col] = packbf(p00, p01);
            *(uint32_t*)&Phi[r1w * 136 + col] = packbf(p10, p11);
            float h00 = __bfloat162float(__float2bfloat16(p00));
            float h01 = __bfloat162float(__float2bfloat16(p01));
            float h10 = __bfloat162float(__float2bfloat16(p10));
            float h11 = __bfloat162float(__float2bfloat16(p11));
            *(uint32_t*)&Plo[r0w * 136 + col] = packbf(p00 - h00, p01 - h01);
            *(uint32_t*)&Plo[r1w * 136 + col] = packbf(p10 - h10, p11 - h11);
        }
        __syncthreads();   // P ready; GEMM1 staging free for V

        // ---- issue V(hc=0); hoist A-frags (Phi/Plo) via ldmatrix ----
#pragma unroll
        for (int x = 0; x < 4; x++) {
            int fid = t + x * 256;
            int hl = fid >> 9, r = (fid >> 4) & 31, s = fid & 15;
            uint32_t st = sb + OVL + hl * 8704;
            const __nv_bfloat16* vsrc = hl ? g_vT_lo : g_vT_hi;
            CP16(st + r * 272 + s * 16, &vsrc[(size_t)r * N + col0 + s * 8]);
        }
        CP_COMMIT();

        uint32_t pa[8][4], pl[8][4];
#pragma unroll
        for (int ks = 0; ks < 8; ks++) {
            ldsm4(pa[ks], sb + 133120 + pld + ks * 32u);
            ldsm4(pl[ks], sb + 150528 + pld + ks * 32u);
        }

        // ---- GEMM2: O[64x512] += P @ V, 16 chunks of 32 H-cols ----
#pragma unroll 1
        for (int hc = 0; hc < 16; hc++) {
            CP_WAIT0();
            __syncthreads();
            if (hc + 1 < 16) {
                uint32_t st = sb + OVL + ((hc + 1) & 1) * 17408;
#pragma unroll
                for (int x = 0; x < 4; x++) {
                    int fid = t + x * 256;
                    int hl = fid >> 9, r = (fid >> 4) & 31, s = fid & 15;
                    const __nv_bfloat16* vsrc = hl ? g_vT_lo : g_vT_hi;
                    CP16(st + hl * 8704 + r * 272 + s * 16,
                         &vsrc[(size_t)((hc + 1) * 32 + r) * N + col0 + s * 8]);
                }
                CP_COMMIT();
            }
            uint32_t vb = sb + OVL + (hc & 1) * 17408;

            float cf[2][4];
            int ob = r0w * 520 + hc * 32 + ch * 16;
#pragma unroll
            for (int nb = 0; nb < 2; nb++) {
                float2 v0 = *(float2*)&Os[ob + nb * 8 + 2 * tig];
                float2 v1 = *(float2*)&Os[ob + 8 * 520 + nb * 8 + 2 * tig];
                cf[nb][0] = v0.x; cf[nb][1] = v0.y;
                cf[nb][2] = v1.x; cf[nb][3] = v1.y;
            }
#pragma unroll
            for (int ks = 0; ks < 8; ks++) {
                uint32_t vh4[4], vl4[4];
                ldsm4(vh4, vb + vld + ks * 32u);
                ldsm4(vl4, vb + 8704 + vld + ks * 32u);
                mma16816(cf[0], pa[ks], vh4[0], vh4[1]);
                mma16816(cf[0], pa[ks], vl4[0], vl4[1]);
                mma16816(cf[0], pl[ks], vh4[0], vh4[1]);
                mma16816(cf[1], pa[ks], vh4[2], vh4[3]);
                mma16816(cf[1], pa[ks], vl4[2], vl4[3]);
                mma16816(cf[1], pl[ks], vh4[2], vh4[3]);
            }
#pragma unroll
            for (int nb = 0; nb < 2; nb++) {
                *(float2*)&Os[ob + nb * 8 + 2 * tig] = make_float2(cf[nb][0], cf[nb][1]);
                *(float2*)&Os[ob + 8 * 520 + nb * 8 + 2 * tig] = make_float2(cf[nb][2], cf[nb][3]);
            }
        }
    }

    // ---- lsum reduce (over tig) and publish ----
    lsum0 += __shfl_xor_sync(0xFFFFFFFFu, lsum0, 1);
    lsum0 += __shfl_xor_sync(0xFFFFFFFFu, lsum0, 2);
    lsum1 += __shfl_xor_sync(0xFFFFFFFFu, lsum1, 1);
    lsum1 += __shfl_xor_sync(0xFFFFFFFFu, lsum1, 2);
    if (tig == 0) {
        lrh[ch * 64 + r0w] = lsum0;
        lrh[ch * 64 + r1w] = lsum1;
    }
    __syncthreads();

    // ---- epilogue: normalize + ELU + scatter rows to original order ----
#pragma unroll 1
    for (int x = 0; x < 32; x++) {
        int fid = t + x * 256;
        int r = fid >> 7, c4 = fid & 127;
        float inv = 1.f / (lrh[r] + lrh[64 + r]);
        float4 v = *(float4*)&Os[r * 520 + c4 * 4];
        v.x *= inv; v.y *= inv; v.z *= inv; v.w *= inv;
        v.x = v.x > 0.f ? v.x : expm1f(v.x);
        v.y = v.y > 0.f ? v.y : expm1f(v.y);
        v.z = v.z > 0.f ? v.z : expm1f(v.z);
        v.w = v.w > 0.f ? v.w : expm1f(v.w);
        *(float4*)&out[(size_t)pr[r] * H + c4 * 4] = v;
    }
}

// ---------------------------------------------------------------------------
extern "C" void kernel_launch(void* const* d_in, const int* in_sizes, int n_in,
                              void* d_out, int out_size) {
    const float* input = (const float*)d_in[0];
    const int*   adj   = (const int*)d_in[1];
    const float* rot   = (const float*)d_in[2];
    const float* kW    = (const float*)d_in[3];
    const float* vW    = (const float*)d_in[4];
    float* out = (float*)d_out;

    const int smem_bytes = 207872;
    cudaFuncSetAttribute(attn_kernel, cudaFuncAttributeMaxDynamicSharedMemorySize,
                         smem_bytes);

    producer_kernel<<<dim3(N / 64, H / 128, 2), 128>>>(input, kW, vW);
    bucket_kernel<<<N / 256, 256>>>(rot);
    hist_kernel<<<32, 256>>>();
    scatter_kernel<<<32, 256>>>();
    conv_kh_kernel<<<(N * H) / 256, 256>>>();
    conv_vT_kernel<<<(H * N) / 256, 256>>>();
    attn_kernel<<<N / 64, 256, smem_bytes>>>(adj, out);
}